// round 1
// baseline (speedup 1.0000x reference)
#include <cuda_runtime.h>
#include <math.h>

#define EPSV 1e-5f
constexpr int B_ = 4, C_ = 64, N_ = 4096, OUT_ = 128, K_ = 20;
constexpr int HB_ = 16;   // C/4

// ---------------- scratch (device globals; no allocation allowed) ----------
__device__ float g_pts[B_ * N_ * C_];     // [B][N][64] transposed points
__device__ float g_sq [B_ * N_];          // squared norms
__device__ float g_hb [B_ * N_ * HB_];    // bottleneck features [B][N][16]
__device__ int   g_idx[B_ * N_ * K_];     // knn indices
__device__ float g_Wres[OUT_ * C_], g_bres[OUT_];
__device__ float g_Wbot[HB_ * C_],  g_bbot[HB_];
__device__ float g_Wg1[32 * 32],    g_bg1[32];
__device__ float g_Wg2[32 * 32],    g_bg2[32];
__device__ float g_Wdec[OUT_ * 96], g_bdec[OUT_];

struct Params { const float* p[26]; };

// ---------------- kernel 0: fold BN into conv weights ----------------------
__global__ void fold_kernel(Params P) {
    const int tid = threadIdx.x;
    {   // res: [128,64]
        const float *W = P.p[1], *g = P.p[2], *b = P.p[3], *m = P.p[4], *v = P.p[5];
        for (int i = tid; i < OUT_ * C_; i += 256) {
            int o = i >> 6;
            float s = g[o] / sqrtf(v[o] + EPSV);
            g_Wres[i] = W[i] * s;
        }
        for (int o = tid; o < OUT_; o += 256) {
            float s = g[o] / sqrtf(v[o] + EPSV);
            g_bres[o] = b[o] - m[o] * s;
        }
    }
    {   // bot: [16,64]
        const float *W = P.p[6], *g = P.p[7], *b = P.p[8], *m = P.p[9], *v = P.p[10];
        for (int i = tid; i < HB_ * C_; i += 256) {
            int o = i >> 6;
            float s = g[o] / sqrtf(v[o] + EPSV);
            g_Wbot[i] = W[i] * s;
        }
        for (int o = tid; o < HB_; o += 256) {
            float s = g[o] / sqrtf(v[o] + EPSV);
            g_bbot[o] = b[o] - m[o] * s;
        }
    }
    {   // g1: [32,32]
        const float *W = P.p[11], *g = P.p[12], *b = P.p[13], *m = P.p[14], *v = P.p[15];
        for (int i = tid; i < 32 * 32; i += 256) {
            int o = i >> 5;
            float s = g[o] / sqrtf(v[o] + EPSV);
            g_Wg1[i] = W[i] * s;
        }
        for (int o = tid; o < 32; o += 256) {
            float s = g[o] / sqrtf(v[o] + EPSV);
            g_bg1[o] = b[o] - m[o] * s;
        }
    }
    {   // g2: [32,32]
        const float *W = P.p[16], *g = P.p[17], *b = P.p[18], *m = P.p[19], *v = P.p[20];
        for (int i = tid; i < 32 * 32; i += 256) {
            int o = i >> 5;
            float s = g[o] / sqrtf(v[o] + EPSV);
            g_Wg2[i] = W[i] * s;
        }
        for (int o = tid; o < 32; o += 256) {
            float s = g[o] / sqrtf(v[o] + EPSV);
            g_bg2[o] = b[o] - m[o] * s;
        }
    }
    {   // dec: [128,96]
        const float *W = P.p[21], *g = P.p[22], *b = P.p[23], *m = P.p[24], *v = P.p[25];
        for (int i = tid; i < OUT_ * 96; i += 256) {
            int o = i / 96;
            float s = g[o] / sqrtf(v[o] + EPSV);
            g_Wdec[i] = W[i] * s;
        }
        for (int o = tid; o < OUT_; o += 256) {
            float s = g[o] / sqrtf(v[o] + EPSV);
            g_bdec[o] = b[o] - m[o] * s;
        }
    }
}

// ---------------- kernel 1: transpose x -> pts, squared norms --------------
__global__ __launch_bounds__(256) void prep_kernel(const float* __restrict__ x) {
    __shared__ float t[64][65];
    const int b = blockIdx.y, n0 = blockIdx.x * 64;
    for (int i = threadIdx.x; i < 64 * 64; i += 256) {
        int c = i >> 6, nn = i & 63;
        t[c][nn] = x[(b * C_ + c) * N_ + n0 + nn];
    }
    __syncthreads();
    for (int i = threadIdx.x; i < 64 * 64; i += 256) {
        int nn = i >> 6, c = i & 63;
        g_pts[(b * N_ + n0 + nn) * C_ + c] = t[c][nn];
    }
    if (threadIdx.x < 64) {
        float s = 0.f;
#pragma unroll
        for (int c = 0; c < 64; c++) { float v = t[c][threadIdx.x]; s += v * v; }
        g_sq[b * N_ + n0 + threadIdx.x] = s;
    }
}

// ---------------- kernel 2: res branch (-> d_out) + bottleneck (-> g_hb) ---
__global__ __launch_bounds__(128) void conv1_kernel(const float* __restrict__ x,
                                                    float* __restrict__ out) {
    __shared__ float WresS[OUT_ * C_];   // 32 KB
    __shared__ float WbotS[HB_ * C_];
    __shared__ float bresS[OUT_], bbotS[HB_];
    const int tid = threadIdx.x;
    const int b = blockIdx.y;
    const int n = blockIdx.x * 128 + tid;
    for (int i = tid; i < OUT_ * C_; i += 128) WresS[i] = g_Wres[i];
    for (int i = tid; i < HB_ * C_; i += 128)  WbotS[i] = g_Wbot[i];
    if (tid < OUT_) bresS[tid] = g_bres[tid];
    if (tid < HB_)  bbotS[tid] = g_bbot[tid];
    __syncthreads();

    float xv[64];
#pragma unroll
    for (int c = 0; c < 64; c++) xv[c] = x[(b * C_ + c) * N_ + n];

#pragma unroll 4
    for (int o = 0; o < OUT_; o++) {
        const float4* w4 = (const float4*)(WresS + o * 64);
        float s0 = 0.f, s1 = 0.f, s2 = 0.f, s3 = 0.f;
#pragma unroll
        for (int i = 0; i < 16; i++) {
            float4 wv = w4[i];
            s0 += wv.x * xv[4 * i + 0];
            s1 += wv.y * xv[4 * i + 1];
            s2 += wv.z * xv[4 * i + 2];
            s3 += wv.w * xv[4 * i + 3];
        }
        float acc = bresS[o] + ((s0 + s1) + (s2 + s3));
        out[(b * OUT_ + o) * N_ + n] = fmaxf(acc, 0.f);
    }
#pragma unroll
    for (int o = 0; o < HB_; o++) {
        const float4* w4 = (const float4*)(WbotS + o * 64);
        float s0 = 0.f, s1 = 0.f, s2 = 0.f, s3 = 0.f;
#pragma unroll
        for (int i = 0; i < 16; i++) {
            float4 wv = w4[i];
            s0 += wv.x * xv[4 * i + 0];
            s1 += wv.y * xv[4 * i + 1];
            s2 += wv.z * xv[4 * i + 2];
            s3 += wv.w * xv[4 * i + 3];
        }
        float acc = bbotS[o] + ((s0 + s1) + (s2 + s3));
        g_hb[(b * N_ + n) * HB_ + o] = fmaxf(acc, 0.f);
    }
}

// ---------------- kernel 3: brute-force KNN (top-20, ties by index) --------
__global__ __launch_bounds__(128) void knn_kernel() {
    __shared__ float tileS[128 * 64];    // 32 KB column tile
    __shared__ float sqS[128];
    const int b = blockIdx.y;
    const int n = blockIdx.x * 128 + threadIdx.x;
    const float* ptsB = g_pts + b * N_ * C_;

    float4 rp4[16];
    {
        const float4* s = (const float4*)(ptsB + n * C_);
#pragma unroll
        for (int i = 0; i < 16; i++) rp4[i] = s[i];
    }
    const float sqr = g_sq[b * N_ + n];

    float kd[K_]; int ki[K_];
#pragma unroll
    for (int k = 0; k < K_; k++) { kd[k] = 3.4e38f; ki[k] = 0; }
    float thr = 3.4e38f;

    for (int ct = 0; ct < N_ / 128; ct++) {
        const int base = ct * 128;
        {
            const float4* src = (const float4*)(ptsB + base * C_);
            float4* dst = (float4*)tileS;
#pragma unroll
            for (int i = 0; i < 16; i++)
                dst[threadIdx.x + i * 128] = src[threadIdx.x + i * 128];
            sqS[threadIdx.x] = g_sq[b * N_ + base + threadIdx.x];
        }
        __syncthreads();
        for (int j = 0; j < 128; j++) {
            const float4* cp = (const float4*)(tileS + j * C_);
            float a0 = 0.f, a1 = 0.f, a2 = 0.f, a3 = 0.f;
#pragma unroll
            for (int i = 0; i < 16; i++) {
                float4 v = cp[i];
                a0 += rp4[i].x * v.x;
                a1 += rp4[i].y * v.y;
                a2 += rp4[i].z * v.z;
                a3 += rp4[i].w * v.w;
            }
            float d2 = sqr + sqS[j] - 2.f * ((a0 + a1) + (a2 + a3));
            if (d2 < thr) {   // strict < keeps lower-index-first on ties (stream order)
                int p = K_ - 1;
                while (p > 0 && kd[p - 1] > d2) {
                    kd[p] = kd[p - 1]; ki[p] = ki[p - 1]; --p;
                }
                kd[p] = d2; ki[p] = base + j;
                thr = kd[K_ - 1];
            }
        }
        __syncthreads();
    }
    int* op = g_idx + (b * N_ + n) * K_;
#pragma unroll
    for (int k = 0; k < K_; k++) op[k] = ki[k];
}

// ---------------- kernel 4: fused GCN (gather, g1, g2, gmax, decode) -------
__device__ __forceinline__ float dot16(const float* wv,
                                       float4 v0, float4 v1, float4 v2, float4 v3) {
    return wv[0] * v0.x + wv[1] * v0.y + wv[2]  * v0.z + wv[3]  * v0.w
         + wv[4] * v1.x + wv[5] * v1.y + wv[6]  * v1.z + wv[7]  * v1.w
         + wv[8] * v2.x + wv[9] * v2.y + wv[10] * v2.z + wv[11] * v2.w
         + wv[12]* v3.x + wv[13]* v3.y + wv[14] * v3.z + wv[15] * v3.w;
}

constexpr int WPB = 8;       // warps (points) per block
constexpr int WD_PAD = 100;  // padded row stride for Wdec (conflict-free float4)

__global__ __launch_bounds__(256) void gcn_kernel(float* __restrict__ out) {
    extern __shared__ float WdP[];              // [128][100] padded decode weights
    __shared__ float nbS[WPB][K_][HB_];
    __shared__ float ctrS[WPB][HB_];
    __shared__ float allfS[WPB][96];
    __shared__ int   idxS[WPB][K_];

    const int tid = threadIdx.x;
    const int w = tid >> 5, lane = tid & 31;
    const int b = blockIdx.y;
    const int n = blockIdx.x * WPB + w;

    for (int i = tid; i < OUT_ * 96; i += 256) {
        int o = i / 96, c = i - o * 96;
        WdP[o * WD_PAD + c] = g_Wdec[i];
    }

    // per-lane rows of folded g1/g2 weights (lane == output channel)
    float w1[32], w2[32];
#pragma unroll
    for (int c = 0; c < 32; c++) { w1[c] = g_Wg1[lane * 32 + c]; w2[c] = g_Wg2[lane * 32 + c]; }
    const float b1 = g_bg1[lane], b2 = g_bg2[lane];

    if (lane < K_)  idxS[w][lane] = g_idx[(b * N_ + n) * K_ + lane];
    if (lane < HB_) ctrS[w][lane] = g_hb[(b * N_ + n) * HB_ + lane];
    __syncwarp();

    for (int t = lane; t < K_ * HB_; t += 32) {
        int k = t >> 4, c = t & 15;
        nbS[w][k][c] = g_hb[(b * N_ + idxS[w][k]) * HB_ + c];
    }
    __syncthreads();   // also covers WdP load

    // center contribution (same for every k)
    float pre1 = b1, pre2 = b2;
#pragma unroll
    for (int c = 0; c < 16; c++) {
        float cv = ctrS[w][c];
        pre1 += w1[16 + c] * cv;
        pre2 += w2[16 + c] * cv;
    }

    float acc1 = -3.4e38f, acc2 = -3.4e38f;
#pragma unroll
    for (int k = 0; k < K_; k++) {
        const float4* nb4 = (const float4*)nbS[w][k];
        float4 v0 = nb4[0], v1 = nb4[1], v2 = nb4[2], v3 = nb4[3];
        float y = pre1 + dot16(w1, v0, v1, v2, v3);
        float ly = y > 0.f ? y : 0.2f * y;
        acc1 = fmaxf(acc1, ly);
        if ((k & 1) == 0) {
            float y2 = pre2 + dot16(w2, v0, v1, v2, v3);
            float ly2 = y2 > 0.f ? y2 : 0.2f * y2;
            acc2 = fmaxf(acc2, ly2);
        }
    }

    // gmax: channels 0..15 = max over neighbors; 16..31 = center (broadcast max)
    float gm = -3.4e38f;
    if (lane < 16) {
#pragma unroll
        for (int k = 0; k < K_; k++) gm = fmaxf(gm, nbS[w][k][lane]);
    }
    allfS[w][lane]      = acc1;
    allfS[w][32 + lane] = acc2;
    allfS[w][64 + lane] = (lane < 16) ? gm : ctrS[w][lane - 16];
    __syncwarp();

    // decode: 128 outputs, lane handles o = lane + 32q
    float accd0 = g_bdec[lane],      accd1 = g_bdec[lane + 32];
    float accd2 = g_bdec[lane + 64], accd3 = g_bdec[lane + 96];
    const float4* af4 = (const float4*)allfS[w];
    const float4* wr0 = (const float4*)(WdP + (lane)      * WD_PAD);
    const float4* wr1 = (const float4*)(WdP + (lane + 32) * WD_PAD);
    const float4* wr2 = (const float4*)(WdP + (lane + 64) * WD_PAD);
    const float4* wr3 = (const float4*)(WdP + (lane + 96) * WD_PAD);
#pragma unroll
    for (int c4 = 0; c4 < 24; c4++) {
        float4 a = af4[c4];
        float4 q0 = wr0[c4]; accd0 += q0.x*a.x + q0.y*a.y + q0.z*a.z + q0.w*a.w;
        float4 q1 = wr1[c4]; accd1 += q1.x*a.x + q1.y*a.y + q1.z*a.z + q1.w*a.w;
        float4 q2 = wr2[c4]; accd2 += q2.x*a.x + q2.y*a.y + q2.z*a.z + q2.w*a.w;
        float4 q3 = wr3[c4]; accd3 += q3.x*a.x + q3.y*a.y + q3.z*a.z + q3.w*a.w;
    }
    {
        int i0 = (b * OUT_ + lane)      * N_ + n;
        int i1 = (b * OUT_ + lane + 32) * N_ + n;
        int i2 = (b * OUT_ + lane + 64) * N_ + n;
        int i3 = (b * OUT_ + lane + 96) * N_ + n;
        float r0 = out[i0], r1 = out[i1], r2 = out[i2], r3 = out[i3];
        out[i0] = fmaxf(accd0, 0.f) + r0;
        out[i1] = fmaxf(accd1, 0.f) + r1;
        out[i2] = fmaxf(accd2, 0.f) + r2;
        out[i3] = fmaxf(accd3, 0.f) + r3;
    }
}

// ---------------- launch ---------------------------------------------------
extern "C" void kernel_launch(void* const* d_in, const int* in_sizes, int n_in,
                              void* d_out, int out_size) {
    Params P;
    for (int i = 0; i < 26; i++) P.p[i] = (const float*)d_in[i];
    const float* x = P.p[0];
    float* out = (float*)d_out;

    cudaFuncSetAttribute(gcn_kernel, cudaFuncAttributeMaxDynamicSharedMemorySize,
                         OUT_ * WD_PAD * (int)sizeof(float));

    fold_kernel<<<1, 256>>>(P);
    prep_kernel<<<dim3(N_ / 64, B_), 256>>>(x);
    conv1_kernel<<<dim3(N_ / 128, B_), 128>>>(x, out);
    knn_kernel<<<dim3(N_ / 128, B_), 128>>>();
    gcn_kernel<<<dim3(N_ / WPB, B_), 256, OUT_ * WD_PAD * (int)sizeof(float)>>>(out);
}